// round 7
// baseline (speedup 1.0000x reference)
#include <cuda_runtime.h>
#include <cstdint>

namespace {
constexpr int T_STEPS = 64;
constexpr int S_DIM = 16;
constexpr int B_DIM = 2048;
constexpr int SB = S_DIM * B_DIM;  // 32768 rows
constexpr int R = 64;              // rows per block
constexpr int NT = 128;
constexpr int P = 68;              // smem row pad (floats): conflict-free frags
}

__device__ float g_cd[B_DIM * 64];  // context @ Wc, [B][Z]

__global__ void ctx_kernel(const float* __restrict__ context,
                           const float* __restrict__ Wc) {
    int idx = blockIdx.x * blockDim.x + threadIdx.x;
    int b = idx >> 6, z = idx & 63;
    float acc = 0.f;
#pragma unroll
    for (int c = 0; c < 64; ++c)
        acc = fmaf(context[b * 64 + c], Wc[c * 64 + z], acc);
    g_cd[idx] = acc;
}

using u64 = unsigned long long;
__device__ __forceinline__ u64 pack2(float x, float y) {
    u64 r; asm("mov.b64 %0, {%1, %2};" : "=l"(r) : "f"(x), "f"(y)); return r;
}
__device__ __forceinline__ void unpack2(u64 v, float& x, float& y) {
    asm("mov.b64 {%0, %1}, %2;" : "=f"(x), "=f"(y) : "l"(v));
}
__device__ __forceinline__ void ffma2(u64& d, u64 a, u64 b) {
    asm("fma.rn.f32x2 %0, %1, %2, %0;" : "+l"(d) : "l"(a), "l"(b));
}
__device__ __forceinline__ u64 ffma2n(u64 a, u64 b, u64 c) {
    u64 d; asm("fma.rn.f32x2 %0, %1, %2, %3;" : "=l"(d) : "l"(a), "l"(b), "l"(c));
    return d;
}
__device__ __forceinline__ u64 add2(u64 a, u64 b) {
    u64 d; asm("add.rn.f32x2 %0, %1, %2;" : "=l"(d) : "l"(a), "l"(b)); return d;
}
__device__ __forceinline__ u64 mul2(u64 a, u64 b) {
    u64 d; asm("mul.rn.f32x2 %0, %1, %2;" : "=l"(d) : "l"(a), "l"(b)); return d;
}
// m16n8k8 tf32 HMMA: D += A(16x8 row) * B(8x8 col)
__device__ __forceinline__ void mma_tf32(float* d, uint32_t a0, uint32_t a1,
                                         uint32_t a2, uint32_t a3,
                                         uint32_t b0, uint32_t b1) {
    asm volatile(
        "mma.sync.aligned.m16n8k8.row.col.f32.tf32.tf32.f32 "
        "{%0,%1,%2,%3}, {%4,%5,%6,%7}, {%8,%9}, {%0,%1,%2,%3};"
        : "+f"(d[0]), "+f"(d[1]), "+f"(d[2]), "+f"(d[3])
        : "r"(a0), "r"(a1), "r"(a2), "r"(a3), "r"(b0), "r"(b1));
}

__global__ void __launch_bounds__(NT, 4) scan_kernel(
    const float* __restrict__ z0, const float* __restrict__ eps,
    const float* __restrict__ W, const float* __restrict__ bvec,
    const float* __restrict__ sigmas, float* __restrict__ out) {
    __shared__ float Wt[64 * P];   // Wt[n][k] = W[k][n] (tf32-rounded)
    __shared__ float zsh[64 * P];  // z[r][k], row-major, pad P
    __shared__ float red[4];

    const int tid = threadIdx.x;
    const int w = tid >> 5;
    const int l = tid & 31;
    const int a = l >> 2;       // fragment groupID
    const int b = l & 3;        // fragment threadID-in-group
    const int rA = w * 16 + a;  // my two rows
    const int rB = rA + 8;
    const int colb = 2 * b;     // base col of my pairs
    const int r0 = blockIdx.x * R;
    const int b0i = r0 & (B_DIM - 1);
    const float dt = 1.0f / T_STEPS;
    const u64 dt2 = pack2(dt, dt);

    // W^T into smem, pre-rounded to tf32
#pragma unroll
    for (int it = 0; it < 4096 / NT; ++it) {
        int idx = tid + it * NT;
        int k = idx >> 6, n = idx & 63;
        float wv = W[idx];
        uint32_t wt;
        asm("cvt.rna.tf32.f32 %0, %1;" : "=r"(wt) : "f"(wv));
        ((uint32_t*)Wt)[n * P + k] = wt;
    }

    float* zs_out = out + 1;  // 4B-aligned only: scalar global stores
    u64 esq2 = 0, usq2 = 0;
    u64 z2[2][8], up2[2][8];

    // init: z0 -> state regs + zsh + z_samples[0] + z0^2
#pragma unroll
    for (int nt = 0; nt < 8; ++nt) {
#pragma unroll
        for (int h = 0; h < 2; ++h) {
            const int row = h ? rB : rA;
            size_t gb = (size_t)(r0 + row) * 64 + colb + 8 * nt;
            float2 zv = *(const float2*)(z0 + gb);
            zs_out[gb] = zv.x; zs_out[gb + 1] = zv.y;
            u64 zz = pack2(zv.x, zv.y);
            ffma2(esq2, zz, zz);
            z2[h][nt] = zz;
            up2[h][nt] = 0;
            *(u64*)(zsh + row * P + colb + 8 * nt) = zz;
        }
    }
    __syncthreads();

    const uint32_t* zshu = (const uint32_t*)zsh;
    const uint32_t* Wtu = (const uint32_t*)Wt;
    u64 dtinvp2 = 0;  // dt/std of previous step (0 => first completion no-op)

#pragma unroll 1
    for (int t = 0; t <= T_STEPS; ++t) {
        // ---- GEMM: drift = z_t @ W via HMMA, D stays in regs ----
        float acc[8][4];
#pragma unroll
        for (int nt = 0; nt < 8; ++nt)
#pragma unroll
            for (int j = 0; j < 4; ++j) acc[nt][j] = 0.f;
#pragma unroll
        for (int ks = 0; ks < 8; ++ks) {
            uint32_t a0 = zshu[rA * P + 8 * ks + b];
            uint32_t a2 = zshu[rA * P + 8 * ks + b + 4];
            uint32_t a1 = zshu[rB * P + 8 * ks + b];
            uint32_t a3 = zshu[rB * P + 8 * ks + b + 4];
#pragma unroll
            for (int nt = 0; nt < 8; ++nt) {
                uint32_t bb0 = Wtu[(8 * nt + a) * P + 8 * ks + b];
                uint32_t bb1 = Wtu[(8 * nt + a) * P + 8 * ks + b + 4];
                mma_tf32(acc[nt], a0, a1, a2, a3, bb0, bb1);
            }
        }

        if (t == T_STEPS) {  // final completion of u(T-1)
#pragma unroll
            for (int nt = 0; nt < 8; ++nt)
#pragma unroll
                for (int h = 0; h < 2; ++h) {
                    u64 d2 = pack2(acc[nt][2 * h], acc[nt][2 * h + 1]);
                    u64 u2 = ffma2n(d2, dtinvp2, up2[h][nt]);
                    ffma2(usq2, u2, u2);
                }
            break;
        }

        // ---- elementwise phase (fragment-aligned state) ----
        const float sig = __ldg(sigmas + t);
        const float stdv = sig * 0.125f;
        const float inv_std = 1.0f / stdv;
        const float dtinv = dt * inv_std;
        const u64 std2 = pack2(stdv, stdv);
        const u64 dtinv2 = pack2(dtinv, dtinv);
        const u64 ndtinv2 = pack2(-dtinv, -dtinv);
        const float* eps_t = eps + (size_t)t * SB * 64;
        float* zo = zs_out + (size_t)(t + 1) * SB * 64;
        const bool last = (t == T_STEPS - 1);

#pragma unroll
        for (int nt = 0; nt < 8; ++nt) {
            float2 btv = __ldg((const float2*)(bvec + t * 64 + colb + 8 * nt));
            u64 bt2 = pack2(btv.x, btv.y);
            u64 btd2 = mul2(bt2, dtinv2);
#pragma unroll
            for (int h = 0; h < 2; ++h) {
                const int row = h ? rB : rA;
                size_t gb = (size_t)(r0 + row) * 64 + colb + 8 * nt;
                u64 d2 = pack2(acc[nt][2 * h], acc[nt][2 * h + 1]);
                // complete u(t-1)
                u64 u2 = ffma2n(d2, dtinvp2, up2[h][nt]);
                ffma2(usq2, u2, u2);
                // forward update
                float2 ev = __ldcs((const float2*)(eps_t + gb));
                float2 cdv = __ldg((const float2*)(
                    g_cd + (size_t)(b0i + row) * 64 + colb + 8 * nt));
                u64 e2 = pack2(ev.x, ev.y);
                u64 cd2 = pack2(cdv.x, cdv.y);
                u64 mu2 = add2(d2, add2(cd2, bt2));
                u64 zn2 = ffma2n(e2, std2, ffma2n(mu2, dt2, z2[h][nt]));
                up2[h][nt] =
                    ffma2n(mu2, ndtinv2, add2(e2 ^ 0x8000000080000000ull, btd2));
                ffma2(esq2, e2, e2);
                if (last) ffma2(usq2, zn2, zn2);
                z2[h][nt] = zn2;
                *(u64*)(zsh + row * P + colb + 8 * nt) = zn2;
                float s0, s1; unpack2(zn2, s0, s1);
                __stcs(zo + gb, s0);      // scalar: zs_out base is
                __stcs(zo + gb + 1, s1);  // only 4-byte aligned
            }
        }
        dtinvp2 = dtinv2;
        __syncwarp();  // my warp's zsh rows visible to my own frag loads
    }

    // reduce lw = (0.5/S) * (esq - usq)
    float e0, e1, q0, q1;
    unpack2(esq2, e0, e1);
    unpack2(usq2, q0, q1);
    float lw = (e0 + e1) - (q0 + q1);
#pragma unroll
    for (int off = 16; off; off >>= 1)
        lw += __shfl_down_sync(0xffffffffu, lw, off);
    if (l == 0) red[w] = lw;
    __syncthreads();
    if (tid == 0) {
        float s = red[0] + red[1] + red[2] + red[3];
        atomicAdd(out, (0.5f / S_DIM) * s);
    }
}

extern "C" void kernel_launch(void* const* d_in, const int* in_sizes, int n_in,
                              void* d_out, int out_size) {
    (void)in_sizes; (void)n_in; (void)out_size;
    const float* z0      = (const float*)d_in[0];
    const float* eps     = (const float*)d_in[1];
    const float* context = (const float*)d_in[2];
    const float* W       = (const float*)d_in[3];
    const float* Wc      = (const float*)d_in[4];
    const float* bvec    = (const float*)d_in[5];
    const float* sigmas  = (const float*)d_in[6];
    float* out = (float*)d_out;

    cudaMemsetAsync(out, 0, sizeof(float));
    ctx_kernel<<<(B_DIM * 64) / 256, 256>>>(context, Wc);
    scan_kernel<<<SB / R, NT>>>(z0, eps, W, bvec, sigmas, out);
}